// round 8
// baseline (speedup 1.0000x reference)
#include <cuda_runtime.h>
#include <cuda_bf16.h>
#include <cuda_fp16.h>
#include <math.h>
#include <stdint.h>

#define NN 50000
#define NE 800000
#define C 128
#define OUTC 16
#define NG 128
#define SB 512
#define NBLK ((NN + SB - 1) / SB)   // 98

// GEMM tiling (tf32 tensor-core)
#define BM 128
#define BK 32
#define SA_STRIDE 36    // floats; bank = (4*row + col) % 32 -> conflict-free frags
#define SW_STRIDE 136   // floats; bank = (8*k + n) % 32   -> conflict-free frags

// -------- device scratch (no allocations allowed) --------
__device__ int   d_is64;
__device__ int   d_cnt[NN];          // incoming-edge counts
__device__ int   d_off[NN + 1];      // CSR offsets
__device__ int   d_cur[NN];          // fill cursors
__device__ int   d_srcs[NE];         // src ids grouped by dst
__device__ int   d_part[256];        // scan partials
__device__ int   d_gcnt[NG];         // nodes per graph
__device__ float d_dis[NN];
__device__ __align__(16) __half d_hp[(size_t)NN * C];
__device__ __align__(16) __half d_h [(size_t)NN * C];

// index accessor: int64 vs int32 edge/batch arrays
__device__ __forceinline__ int eidx(const void* p, int pos) {
    return d_is64 ? (int)((const long long*)p)[pos] : ((const int*)p)[pos];
}

__device__ __forceinline__ uint32_t f2tf32(float x) {
    uint32_t r;
    asm("cvt.rna.tf32.f32 %0, %1;" : "=r"(r) : "f"(x));
    return r;
}

__device__ __forceinline__ float4 h4tof4(uint2 u) {
    __half2 a = *reinterpret_cast<__half2*>(&u.x);
    __half2 b = *reinterpret_cast<__half2*>(&u.y);
    float2 fa = __half22float2(a), fb = __half22float2(b);
    return make_float4(fa.x, fa.y, fb.x, fb.y);
}

__device__ __forceinline__ void h8tof8(uint4 u, float* f) {
    float2 a = __half22float2(*reinterpret_cast<__half2*>(&u.x));
    float2 b = __half22float2(*reinterpret_cast<__half2*>(&u.y));
    float2 c = __half22float2(*reinterpret_cast<__half2*>(&u.z));
    float2 d = __half22float2(*reinterpret_cast<__half2*>(&u.w));
    f[0] = a.x; f[1] = a.y; f[2] = b.x; f[3] = b.y;
    f[4] = c.x; f[5] = c.y; f[6] = d.x; f[7] = d.y;
}

// ---------------------------------------------------------------------------
// setup: zero counters; thread 0 sniffs index dtype (int64 high words == 0)
__global__ void k_setup(const unsigned int* __restrict__ w) {
    int i = blockIdx.x * blockDim.x + threadIdx.x;
    if (i == 0) {
        int allz = 1;
        #pragma unroll
        for (int j = 0; j < 32; j++)
            if (w[2 * j + 1] != 0u) allz = 0;
        d_is64 = allz;
    }
    if (i < NN) d_cnt[i] = 0;
    if (i < NG) d_gcnt[i] = 0;
}

// fused: count incoming edges per dst + per-graph node counts
__global__ void k_count_gcnt(const void* __restrict__ ei, const void* __restrict__ batch) {
    int i = blockIdx.x * blockDim.x + threadIdx.x;
    if (i < NE) atomicAdd(&d_cnt[eidx(ei, NE + i)], 1);
    if (i < NN) atomicAdd(&d_gcnt[eidx(batch, i)], 1);
}

// scan stage 1 (shfl-based): per-block exclusive scan of d_cnt -> d_off
__global__ void k_scan1() {
    __shared__ int wsum[16];
    int t = threadIdx.x;
    int i = blockIdx.x * SB + t;
    int v = (i < NN) ? d_cnt[i] : 0;
    int x = v;
    #pragma unroll
    for (int o = 1; o < 32; o <<= 1) {
        int y = __shfl_up_sync(0xffffffffu, x, o);
        if ((t & 31) >= o) x += y;
    }
    if ((t & 31) == 31) wsum[t >> 5] = x;
    __syncthreads();
    if (t < 16) {
        int y = wsum[t];
        #pragma unroll
        for (int o = 1; o < 16; o <<= 1) {
            int z = __shfl_up_sync(0xffffu, y, o);
            if (t >= o) y += z;
        }
        wsum[t] = y;
    }
    __syncthreads();
    int base = (t >= 32) ? wsum[(t >> 5) - 1] : 0;
    int incl = x + base;
    if (i < NN) d_off[i] = incl - v;            // exclusive
    if (t == SB - 1) d_part[blockIdx.x] = incl; // block total
}

// scan stage 3: each block reduces the partials it needs (no scan2 kernel),
// adds block offsets, inits cursors, computes dis = rsqrt(deg)
__global__ void k_scan3() {
    __shared__ int sbase;
    int b512 = (blockIdx.x * 256) >> 9;   // owning scan1 block (256-node blocks)
    if (threadIdx.x < 32) {
        int sum = 0;
        for (int j = threadIdx.x; j < b512; j += 32) sum += d_part[j];
        #pragma unroll
        for (int o = 16; o > 0; o >>= 1) sum += __shfl_down_sync(0xffffffffu, sum, o);
        if (threadIdx.x == 0) sbase = sum;
    }
    __syncthreads();
    int i = blockIdx.x * 256 + threadIdx.x;
    if (i < NN) {
        int o = d_off[i] + sbase;
        d_off[i] = o;
        d_cur[i] = o;
        d_dis[i] = rsqrtf((float)(d_cnt[i] + 1));   // +1 self loop
    }
    if (i == 0) d_off[NN] = NE;
}

// fill CSR: srcs grouped by dst
__global__ void k_fill(const void* __restrict__ ei) {
    int e = blockIdx.x * blockDim.x + threadIdx.x;
    if (e >= NE) return;
    int s = eidx(ei, e);
    int d = eidx(ei, NE + e);
    int slot = atomicAdd(&d_cur[d], 1);
    d_srcs[slot] = s;
}

// ---------------------------------------------------------------------------
// TF32 tensor-core GEMM: hp(half) = A @ W (UNSCALED; dis applied in agg).
// 128x128 block tile, 256 threads = 8 warps (2x4), warp tile 64x32.
template <typename T>
__global__ void __launch_bounds__(256)
k_gemm(const T* __restrict__ A, const float* __restrict__ W,
       __half* __restrict__ hp, int n) {
    __shared__ uint32_t sA[BM * SA_STRIDE];   // tf32 bits, row-major, stride 36
    __shared__ uint32_t sW[BK * SW_STRIDE];   // tf32 bits, k-major, stride 136

    int tid = threadIdx.x;
    int lane = tid & 31;
    int wid = tid >> 5;
    int wm = wid >> 2;          // 0..1 : rows [wm*64, wm*64+64)
    int wn = wid & 3;           // 0..3 : cols [wn*32, wn*32+32)
    int g  = lane >> 2;         // groupID 0..7
    int tg = lane & 3;          // threadID-in-group 0..3
    int row0 = blockIdx.x * BM;

    float acc[4][4][4];         // [m-frag][n-frag][reg]
    #pragma unroll
    for (int i = 0; i < 4; i++)
        #pragma unroll
        for (int j = 0; j < 4; j++)
            #pragma unroll
            for (int r = 0; r < 4; r++) acc[i][j][r] = 0.0f;

    for (int kc = 0; kc < C / BK; kc++) {
        __syncthreads();
        // stage A chunk: 128 rows x 32 k; cvt to tf32
        #pragma unroll
        for (int p = 0; p < 4; p++) {
            int idx = tid + p * 256;        // 0..1023
            int r = idx >> 3;               // 0..127
            int c4 = idx & 7;               // 0..7
            int gr = row0 + r;
            float4 v = make_float4(0.f, 0.f, 0.f, 0.f);
            if (gr < n) {
                if constexpr (sizeof(T) == 4) {
                    v = *(const float4*)((const float*)A + (size_t)gr * C + kc * BK + c4 * 4);
                } else {
                    uint2 u = *(const uint2*)((const __half*)A + (size_t)gr * C + kc * BK + c4 * 4);
                    v = h4tof4(u);
                }
            }
            uint32_t* dst = sA + r * SA_STRIDE + c4 * 4;
            dst[0] = f2tf32(v.x); dst[1] = f2tf32(v.y);
            dst[2] = f2tf32(v.z); dst[3] = f2tf32(v.w);
        }
        // stage W chunk: 32 k x 128 n
        #pragma unroll
        for (int p = 0; p < 4; p++) {
            int idx = tid + p * 256;
            int k = idx >> 5;               // 0..31
            int n4 = idx & 31;              // 0..31
            float4 v = *(const float4*)(W + (size_t)(kc * BK + k) * C + n4 * 4);
            uint32_t* dst = sW + k * SW_STRIDE + n4 * 4;
            dst[0] = f2tf32(v.x); dst[1] = f2tf32(v.y);
            dst[2] = f2tf32(v.z); dst[3] = f2tf32(v.w);
        }
        __syncthreads();

        #pragma unroll
        for (int ks = 0; ks < BK / 8; ks++) {
            int kb = ks * 8;
            uint32_t bf[4][2];
            #pragma unroll
            for (int nt = 0; nt < 4; nt++) {
                int nn = wn * 32 + nt * 8 + g;
                bf[nt][0] = sW[(kb + tg) * SW_STRIDE + nn];
                bf[nt][1] = sW[(kb + tg + 4) * SW_STRIDE + nn];
            }
            uint32_t af[4][4];
            #pragma unroll
            for (int mt = 0; mt < 4; mt++) {
                int rbase = wm * 64 + mt * 16;
                af[mt][0] = sA[(rbase + g)     * SA_STRIDE + kb + tg];
                af[mt][1] = sA[(rbase + g + 8) * SA_STRIDE + kb + tg];
                af[mt][2] = sA[(rbase + g)     * SA_STRIDE + kb + tg + 4];
                af[mt][3] = sA[(rbase + g + 8) * SA_STRIDE + kb + tg + 4];
            }
            #pragma unroll
            for (int mt = 0; mt < 4; mt++)
                #pragma unroll
                for (int nt = 0; nt < 4; nt++) {
                    asm volatile(
                        "mma.sync.aligned.m16n8k8.row.col.f32.tf32.tf32.f32 "
                        "{%0,%1,%2,%3}, {%4,%5,%6,%7}, {%8,%9}, {%0,%1,%2,%3};"
                        : "+f"(acc[mt][nt][0]), "+f"(acc[mt][nt][1]),
                          "+f"(acc[mt][nt][2]), "+f"(acc[mt][nt][3])
                        : "r"(af[mt][0]), "r"(af[mt][1]), "r"(af[mt][2]), "r"(af[mt][3]),
                          "r"(bf[nt][0]), "r"(bf[nt][1]));
                }
        }
    }

    // epilogue: store half2 pairs (unscaled)
    #pragma unroll
    for (int mt = 0; mt < 4; mt++) {
        int r0 = row0 + wm * 64 + mt * 16 + g;
        int r1 = r0 + 8;
        #pragma unroll
        for (int nt = 0; nt < 4; nt++) {
            int col = wn * 32 + nt * 8 + tg * 2;
            if (r0 < n) {
                __half2 o = __floats2half2_rn(acc[mt][nt][0], acc[mt][nt][1]);
                *(__half2*)(hp + (size_t)r0 * C + col) = o;
            }
            if (r1 < n) {
                __half2 o = __floats2half2_rn(acc[mt][nt][2], acc[mt][nt][3]);
                *(__half2*)(hp + (size_t)r1 * C + col) = o;
            }
        }
    }
}

// ---------------------------------------------------------------------------
// Aggregate (gather, no atomics): 16-lane group per dst node, LDG.128.
// h[v] = relu( dis[v] * (dis[v]*hp[v] + sum_e dis[s]*hp[s]) + b )
__global__ void k_agg(const __half* __restrict__ hp, const float* __restrict__ b,
                      __half* __restrict__ h) {
    int v = (blockIdx.x * blockDim.x + threadIdx.x) >> 4;
    if (v >= NN) return;
    int lane = threadIdx.x & 15;       // 8 channels per lane

    float dv = d_dis[v];
    float acc[8];
    {
        float f[8];
        h8tof8(*(const uint4*)(hp + (size_t)v * C + lane * 8), f);
        #pragma unroll
        for (int j = 0; j < 8; j++) acc[j] = dv * f[j];   // self loop
    }
    int e = d_off[v], end = d_off[v + 1];

    for (; e + 3 < end; e += 4) {
        int s0 = __ldg(&d_srcs[e]),     s1 = __ldg(&d_srcs[e + 1]);
        int s2 = __ldg(&d_srcs[e + 2]), s3 = __ldg(&d_srcs[e + 3]);
        float w0 = __ldg(&d_dis[s0]), w1 = __ldg(&d_dis[s1]);
        float w2 = __ldg(&d_dis[s2]), w3 = __ldg(&d_dis[s3]);
        uint4 u0 = *(const uint4*)(hp + (size_t)s0 * C + lane * 8);
        uint4 u1 = *(const uint4*)(hp + (size_t)s1 * C + lane * 8);
        uint4 u2 = *(const uint4*)(hp + (size_t)s2 * C + lane * 8);
        uint4 u3 = *(const uint4*)(hp + (size_t)s3 * C + lane * 8);
        float f0[8], f1[8], f2[8], f3[8];
        h8tof8(u0, f0); h8tof8(u1, f1); h8tof8(u2, f2); h8tof8(u3, f3);
        #pragma unroll
        for (int j = 0; j < 8; j++)
            acc[j] += w0 * f0[j] + w1 * f1[j] + w2 * f2[j] + w3 * f3[j];
    }
    for (; e < end; e++) {
        int s = __ldg(&d_srcs[e]);
        float w = __ldg(&d_dis[s]);
        float f[8];
        h8tof8(*(const uint4*)(hp + (size_t)s * C + lane * 8), f);
        #pragma unroll
        for (int j = 0; j < 8; j++) acc[j] += w * f[j];
    }

    float4 bb0 = ((const float4*)b)[lane * 2];
    float4 bb1 = ((const float4*)b)[lane * 2 + 1];
    float bbv[8] = {bb0.x, bb0.y, bb0.z, bb0.w, bb1.x, bb1.y, bb1.z, bb1.w};
    __half2 o[4];
    #pragma unroll
    for (int j = 0; j < 4; j++) {
        float x0 = fmaxf(fmaf(dv, acc[2 * j],     bbv[2 * j]),     0.0f);
        float x1 = fmaxf(fmaf(dv, acc[2 * j + 1], bbv[2 * j + 1]), 0.0f);
        o[j] = __floats2half2_rn(x0, x1);
    }
    *(uint4*)(h + (size_t)v * C + lane * 8) = *reinterpret_cast<uint4*>(o);
}

// ---------------------------------------------------------------------------
// Fused pool + FC head + log_softmax. batch sorted -> graph g owns contiguous
// node range; each block computes the 128-graph prefix of gcnt inline.
__global__ void k_poolhead(const __half* __restrict__ h, const float* __restrict__ Wfc,
                           const float* __restrict__ bfc, float* __restrict__ out) {
    int g = blockIdx.x;
    int t = threadIdx.x;   // 128
    __shared__ float sp[C];
    __shared__ float sl[OUTC];
    __shared__ float s_m, s_lse;
    __shared__ int sincl[NG];
    __shared__ int wtot[4];

    // inline exclusive/inclusive prefix of d_gcnt (128 values, 4 warps)
    int cv = d_gcnt[t];
    int x = cv;
    #pragma unroll
    for (int o = 1; o < 32; o <<= 1) {
        int y = __shfl_up_sync(0xffffffffu, x, o);
        if ((t & 31) >= o) x += y;
    }
    if ((t & 31) == 31) wtot[t >> 5] = x;
    __syncthreads();
    int base = 0;
    #pragma unroll
    for (int wj = 0; wj < 4; wj++)
        if (wj < (t >> 5)) base += wtot[wj];
    sincl[t] = x + base;
    __syncthreads();

    int r1 = sincl[g];
    int r0 = (g > 0) ? sincl[g - 1] : 0;

    float a0 = 0.0f, a1 = 0.0f;
    int r = r0;
    for (; r + 1 < r1; r += 2) {
        a0 += __half2float(h[(size_t)r * C + t]);
        a1 += __half2float(h[(size_t)(r + 1) * C + t]);
    }
    if (r < r1) a0 += __half2float(h[(size_t)r * C + t]);
    float cnt = fmaxf((float)(r1 - r0), 1.0f);
    sp[t] = (a0 + a1) / cnt;
    __syncthreads();

    if (t < OUTC) {
        float a = bfc[t];
        #pragma unroll 8
        for (int k = 0; k < C; k++) a += sp[k] * Wfc[k * OUTC + t];
        sl[t] = a;
    }
    __syncthreads();
    if (t == 0) {
        float mx = sl[0];
        #pragma unroll
        for (int j = 1; j < OUTC; j++) mx = fmaxf(mx, sl[j]);
        float s = 0.0f;
        #pragma unroll
        for (int j = 0; j < OUTC; j++) s += expf(sl[j] - mx);
        s_m = mx;
        s_lse = logf(s);
    }
    __syncthreads();
    if (t < OUTC) out[g * OUTC + t] = sl[t] - s_m - s_lse;
}

// ---------------------------------------------------------------------------
extern "C" void kernel_launch(void* const* d_in, const int* in_sizes, int n_in,
                              void* d_out, int out_size) {
    const float* x     = (const float*)d_in[0];
    const void*  ei    = d_in[1];
    const void*  batch = d_in[2];
    const float* W1    = (const float*)d_in[3];
    const float* b1    = (const float*)d_in[4];
    const float* W2    = (const float*)d_in[5];
    const float* b2    = (const float*)d_in[6];
    const float* Wfc   = (const float*)d_in[7];
    const float* bfc   = (const float*)d_in[8];
    float* out = (float*)d_out;

    __half *hp, *h;
    cudaGetSymbolAddress((void**)&hp, d_hp);
    cudaGetSymbolAddress((void**)&h, d_h);

    static cudaStream_t s_side = nullptr;
    static cudaEvent_t ev_fork = nullptr, ev_join = nullptr;
    if (!s_side) {
        cudaStreamCreateWithFlags(&s_side, cudaStreamNonBlocking);
        cudaEventCreateWithFlags(&ev_fork, cudaEventDisableTiming);
        cudaEventCreateWithFlags(&ev_join, cudaEventDisableTiming);
    }

    // Fork: CSR build on side stream, GEMM1 (independent of it) on main stream.
    cudaEventRecord(ev_fork, 0);
    cudaStreamWaitEvent(s_side, ev_fork, 0);

    k_setup<<<(NN + 255) / 256, 256, 0, s_side>>>((const unsigned int*)ei);
    k_count_gcnt<<<(NE + 255) / 256, 256, 0, s_side>>>(ei, batch);
    k_scan1<<<NBLK, SB, 0, s_side>>>();
    k_scan3<<<(NN + 255) / 256, 256, 0, s_side>>>();
    k_fill<<<(NE + 255) / 256, 256, 0, s_side>>>(ei);
    cudaEventRecord(ev_join, s_side);

    k_gemm<float><<<(NN + BM - 1) / BM, 256>>>(x, W1, hp, NN);

    // Join: agg needs both GEMM1 output and the CSR/dis.
    cudaStreamWaitEvent(0, ev_join, 0);

    k_agg<<<(NN * 16 + 255) / 256, 256>>>(hp, b1, h);

    // layer 2
    k_gemm<__half><<<(NN + BM - 1) / BM, 256>>>(h, W2, hp, NN);
    k_agg<<<(NN * 16 + 255) / 256, 256>>>(hp, b2, h);

    // fused pool + head
    k_poolhead<<<NG, C>>>(h, Wfc, bfc, out);
}

// round 9
// speedup vs baseline: 1.0838x; 1.0838x over previous
#include <cuda_runtime.h>
#include <cuda_fp16.h>
#include <math.h>
#include <stdint.h>

#define NN 50000
#define NE 800000
#define C 128
#define OUTC 16
#define NG 128
#define SB 512
#define NBLK ((NN + SB - 1) / SB)   // 98

// GEMM tiling (tf32 tensor-core)
#define BM 128
#define BK 32
#define SA_STRIDE 36    // floats; bank = (4*row + col) % 32 -> conflict-free frags
#define SW_STRIDE 136   // floats; bank = (8*k + n) % 32   -> conflict-free frags

// -------- device scratch (no allocations allowed) --------
__device__ int   d_is64;
__device__ int   d_cnt[NN];          // incoming-edge counts
__device__ int   d_off[NN + 1];      // CSR offsets
__device__ int   d_cur[NN];          // fill cursors
__device__ int   d_srcs[NE];         // src ids grouped by dst
__device__ int   d_state[NBLK];      // lookback state: 0=none,1=agg,2=prefix
__device__ int   d_aggv[NBLK];       // block aggregate
__device__ int   d_prefv[NBLK];      // block inclusive prefix
__device__ int   d_gcnt[NG];         // nodes per graph
__device__ float d_dis[NN];
__device__ __align__(16) __half d_hp[(size_t)NN * C];
__device__ __align__(16) __half d_h [(size_t)NN * C];

// index accessor: int64 vs int32 edge/batch arrays
__device__ __forceinline__ int eidx(const void* p, int pos) {
    return d_is64 ? (int)((const long long*)p)[pos] : ((const int*)p)[pos];
}

__device__ __forceinline__ uint32_t f2tf32(float x) {
    uint32_t r;
    asm("cvt.rna.tf32.f32 %0, %1;" : "=r"(r) : "f"(x));
    return r;
}

__device__ __forceinline__ float4 h4tof4(uint2 u) {
    __half2 a = *reinterpret_cast<__half2*>(&u.x);
    __half2 b = *reinterpret_cast<__half2*>(&u.y);
    float2 fa = __half22float2(a), fb = __half22float2(b);
    return make_float4(fa.x, fa.y, fb.x, fb.y);
}

__device__ __forceinline__ uint2 f4toh4(float4 f) {
    __half2 a = __floats2half2_rn(f.x, f.y);
    __half2 b = __floats2half2_rn(f.z, f.w);
    uint2 u;
    u.x = *reinterpret_cast<uint32_t*>(&a);
    u.y = *reinterpret_cast<uint32_t*>(&b);
    return u;
}

// ---------------------------------------------------------------------------
// setup: zero counters + lookback state; thread 0 sniffs index dtype
__global__ void k_setup(const unsigned int* __restrict__ w) {
    int i = blockIdx.x * blockDim.x + threadIdx.x;
    if (i == 0) {
        int allz = 1;
        #pragma unroll
        for (int j = 0; j < 32; j++)
            if (w[2 * j + 1] != 0u) allz = 0;
        d_is64 = allz;
    }
    if (i < NN) d_cnt[i] = 0;
    if (i < NG) d_gcnt[i] = 0;
    if (i < NBLK) d_state[i] = 0;
}

// fused: count incoming edges per dst + per-graph node counts
__global__ void k_count_gcnt(const void* __restrict__ ei, const void* __restrict__ batch) {
    int i = blockIdx.x * blockDim.x + threadIdx.x;
    if (i < NE) atomicAdd(&d_cnt[eidx(ei, NE + i)], 1);
    if (i < NN) atomicAdd(&d_gcnt[eidx(batch, i)], 1);
}

// ---------------------------------------------------------------------------
// Single-pass decoupled-lookback exclusive scan of d_cnt -> d_off;
// also inits cursors and dis = rsqrt(deg+1).
__global__ void k_scan() {
    __shared__ int wsum[16];
    __shared__ int stotal;
    __shared__ int sbase;
    int b = blockIdx.x;
    int t = threadIdx.x;
    int i = b * SB + t;
    int v = (i < NN) ? d_cnt[i] : 0;

    // intra-block inclusive scan
    int x = v;
    #pragma unroll
    for (int o = 1; o < 32; o <<= 1) {
        int y = __shfl_up_sync(0xffffffffu, x, o);
        if ((t & 31) >= o) x += y;
    }
    if ((t & 31) == 31) wsum[t >> 5] = x;
    __syncthreads();
    if (t < 16) {
        int y = wsum[t];
        #pragma unroll
        for (int o = 1; o < 16; o <<= 1) {
            int z = __shfl_up_sync(0xffffu, y, o);
            if (t >= o) y += z;
        }
        wsum[t] = y;
    }
    __syncthreads();
    int wbase = (t >= 32) ? wsum[(t >> 5) - 1] : 0;
    int incl = x + wbase;
    if (t == SB - 1) stotal = incl;
    __syncthreads();

    // publish aggregate (or prefix for block 0)
    if (t == 0) {
        if (b == 0) {
            d_prefv[0] = stotal;
            __threadfence();
            *(volatile int*)&d_state[0] = 2;
        } else {
            d_aggv[b] = stotal;
            __threadfence();
            *(volatile int*)&d_state[b] = 1;
        }
        if (b == 0) sbase = 0;
    }

    // warp 0 performs decoupled lookback
    if (b > 0 && t < 32) {
        int sum = 0;
        int j = b - 1;
        while (true) {
            int jj = j - t;
            int st = (jj >= 0) ? *(volatile int*)&d_state[jj] : 2;
            while (__any_sync(0xffffffffu, st == 0)) {
                st = (jj >= 0) ? *(volatile int*)&d_state[jj] : 2;
            }
            __threadfence();
            unsigned mask2 = __ballot_sync(0xffffffffu, st == 2 && jj >= 0);
            int val;
            bool done;
            if (mask2) {
                int lead = __ffs(mask2) - 1;       // smallest lane = largest jj with prefix
                if (t < lead)       val = *(volatile int*)&d_aggv[jj];
                else if (t == lead) val = *(volatile int*)&d_prefv[jj];
                else                val = 0;
                done = true;
            } else {
                val = (jj >= 0) ? *(volatile int*)&d_aggv[jj] : 0;
                done = false;
            }
            #pragma unroll
            for (int o = 16; o > 0; o >>= 1) val += __shfl_down_sync(0xffffffffu, val, o);
            val = __shfl_sync(0xffffffffu, val, 0);
            sum += val;
            if (done) break;
            j -= 32;
        }
        if (t == 0) {
            sbase = sum;
            d_prefv[b] = sum + stotal;
            __threadfence();
            *(volatile int*)&d_state[b] = 2;
        }
    }
    __syncthreads();

    int base = sbase;
    if (i < NN) {
        int o = incl - v + base;     // exclusive global prefix
        d_off[i] = o;
        d_cur[i] = o;
        d_dis[i] = rsqrtf((float)(v + 1));   // +1 self loop
    }
    if (i == 0) d_off[NN] = NE;
}

// fill CSR: srcs grouped by dst
__global__ void k_fill(const void* __restrict__ ei) {
    int e = blockIdx.x * blockDim.x + threadIdx.x;
    if (e >= NE) return;
    int s = eidx(ei, e);
    int d = eidx(ei, NE + e);
    int slot = atomicAdd(&d_cur[d], 1);
    d_srcs[slot] = s;
}

// ---------------------------------------------------------------------------
// TF32 tensor-core GEMM: hp(half) = dis[:,None] * (A @ W), A fp32 or fp16.
// 128x128 block tile, 256 threads = 8 warps (2x4), warp tile 64x32.
template <typename T>
__global__ void __launch_bounds__(256)
k_gemm(const T* __restrict__ A, const float* __restrict__ W,
       __half* __restrict__ hp, int n) {
    __shared__ uint32_t sA[BM * SA_STRIDE];   // tf32 bits, row-major, stride 36
    __shared__ uint32_t sW[BK * SW_STRIDE];   // tf32 bits, k-major, stride 136

    int tid = threadIdx.x;
    int lane = tid & 31;
    int wid = tid >> 5;
    int wm = wid >> 2;          // 0..1 : rows [wm*64, wm*64+64)
    int wn = wid & 3;           // 0..3 : cols [wn*32, wn*32+32)
    int g  = lane >> 2;         // groupID 0..7
    int tg = lane & 3;          // threadID-in-group 0..3
    int row0 = blockIdx.x * BM;

    float acc[4][4][4];         // [m-frag][n-frag][reg]
    #pragma unroll
    for (int i = 0; i < 4; i++)
        #pragma unroll
        for (int j = 0; j < 4; j++)
            #pragma unroll
            for (int r = 0; r < 4; r++) acc[i][j][r] = 0.0f;

    for (int kc = 0; kc < C / BK; kc++) {
        __syncthreads();
        // stage A chunk: 128 rows x 32 k; cvt to tf32
        #pragma unroll
        for (int p = 0; p < 4; p++) {
            int idx = tid + p * 256;        // 0..1023
            int r = idx >> 3;               // 0..127
            int c4 = idx & 7;               // 0..7
            int gr = row0 + r;
            float4 v = make_float4(0.f, 0.f, 0.f, 0.f);
            if (gr < n) {
                if constexpr (sizeof(T) == 4) {
                    v = *(const float4*)((const float*)A + (size_t)gr * C + kc * BK + c4 * 4);
                } else {
                    uint2 u = *(const uint2*)((const __half*)A + (size_t)gr * C + kc * BK + c4 * 4);
                    v = h4tof4(u);
                }
            }
            uint32_t* dst = sA + r * SA_STRIDE + c4 * 4;
            dst[0] = f2tf32(v.x); dst[1] = f2tf32(v.y);
            dst[2] = f2tf32(v.z); dst[3] = f2tf32(v.w);
        }
        // stage W chunk: 32 k x 128 n
        #pragma unroll
        for (int p = 0; p < 4; p++) {
            int idx = tid + p * 256;
            int k = idx >> 5;               // 0..31
            int n4 = idx & 31;              // 0..31
            float4 v = *(const float4*)(W + (size_t)(kc * BK + k) * C + n4 * 4);
            uint32_t* dst = sW + k * SW_STRIDE + n4 * 4;
            dst[0] = f2tf32(v.x); dst[1] = f2tf32(v.y);
            dst[2] = f2tf32(v.z); dst[3] = f2tf32(v.w);
        }
        __syncthreads();

        #pragma unroll
        for (int ks = 0; ks < BK / 8; ks++) {
            int kb = ks * 8;
            uint32_t bf[4][2];
            #pragma unroll
            for (int nt = 0; nt < 4; nt++) {
                int nn = wn * 32 + nt * 8 + g;
                bf[nt][0] = sW[(kb + tg) * SW_STRIDE + nn];
                bf[nt][1] = sW[(kb + tg + 4) * SW_STRIDE + nn];
            }
            uint32_t af[4][4];
            #pragma unroll
            for (int mt = 0; mt < 4; mt++) {
                int rbase = wm * 64 + mt * 16;
                af[mt][0] = sA[(rbase + g)     * SA_STRIDE + kb + tg];
                af[mt][1] = sA[(rbase + g + 8) * SA_STRIDE + kb + tg];
                af[mt][2] = sA[(rbase + g)     * SA_STRIDE + kb + tg + 4];
                af[mt][3] = sA[(rbase + g + 8) * SA_STRIDE + kb + tg + 4];
            }
            #pragma unroll
            for (int mt = 0; mt < 4; mt++)
                #pragma unroll
                for (int nt = 0; nt < 4; nt++) {
                    asm volatile(
                        "mma.sync.aligned.m16n8k8.row.col.f32.tf32.tf32.f32 "
                        "{%0,%1,%2,%3}, {%4,%5,%6,%7}, {%8,%9}, {%0,%1,%2,%3};"
                        : "+f"(acc[mt][nt][0]), "+f"(acc[mt][nt][1]),
                          "+f"(acc[mt][nt][2]), "+f"(acc[mt][nt][3])
                        : "r"(af[mt][0]), "r"(af[mt][1]), "r"(af[mt][2]), "r"(af[mt][3]),
                          "r"(bf[nt][0]), "r"(bf[nt][1]));
                }
        }
    }

    // epilogue: scale by dis[row], store half2 pairs
    #pragma unroll
    for (int mt = 0; mt < 4; mt++) {
        int r0 = row0 + wm * 64 + mt * 16 + g;
        int r1 = r0 + 8;
        float ds0 = (r0 < n) ? d_dis[r0] : 0.0f;
        float ds1 = (r1 < n) ? d_dis[r1] : 0.0f;
        #pragma unroll
        for (int nt = 0; nt < 4; nt++) {
            int col = wn * 32 + nt * 8 + tg * 2;
            if (r0 < n) {
                __half2 o = __floats2half2_rn(acc[mt][nt][0] * ds0, acc[mt][nt][1] * ds0);
                *(__half2*)(hp + (size_t)r0 * C + col) = o;
            }
            if (r1 < n) {
                __half2 o = __floats2half2_rn(acc[mt][nt][2] * ds1, acc[mt][nt][3] * ds1);
                *(__half2*)(hp + (size_t)r1 * C + col) = o;
            }
        }
    }
}

// ---------------------------------------------------------------------------
// Aggregate (gather, no atomics): one warp per dst node, fp16 in/out, fp32 acc.
// h[v] = relu( dis[v] * (hp[v] + sum_{e in(v)} hp[src_e]) + b )
__global__ void k_agg(const __half* __restrict__ hp, const float* __restrict__ b,
                      __half* __restrict__ h) {
    int v = (blockIdx.x * blockDim.x + threadIdx.x) >> 5;
    if (v >= NN) return;
    int lane = threadIdx.x & 31;

    float4 acc = h4tof4(*(const uint2*)(hp + (size_t)v * C + lane * 4));  // self loop
    int e = d_off[v], end = d_off[v + 1];

    for (; e + 3 < end; e += 4) {
        int s0 = d_srcs[e], s1 = d_srcs[e + 1], s2 = d_srcs[e + 2], s3 = d_srcs[e + 3];
        float4 m0 = h4tof4(*(const uint2*)(hp + (size_t)s0 * C + lane * 4));
        float4 m1 = h4tof4(*(const uint2*)(hp + (size_t)s1 * C + lane * 4));
        float4 m2 = h4tof4(*(const uint2*)(hp + (size_t)s2 * C + lane * 4));
        float4 m3 = h4tof4(*(const uint2*)(hp + (size_t)s3 * C + lane * 4));
        acc.x += m0.x + m1.x + m2.x + m3.x;
        acc.y += m0.y + m1.y + m2.y + m3.y;
        acc.z += m0.z + m1.z + m2.z + m3.z;
        acc.w += m0.w + m1.w + m2.w + m3.w;
    }
    for (; e < end; e++) {
        int s = d_srcs[e];
        float4 m = h4tof4(*(const uint2*)(hp + (size_t)s * C + lane * 4));
        acc.x += m.x; acc.y += m.y; acc.z += m.z; acc.w += m.w;
    }

    float ds = d_dis[v];
    float4 bb = ((const float4*)b)[lane];
    float4 o;
    o.x = fmaxf(fmaf(ds, acc.x, bb.x), 0.0f);
    o.y = fmaxf(fmaf(ds, acc.y, bb.y), 0.0f);
    o.z = fmaxf(fmaf(ds, acc.z, bb.z), 0.0f);
    o.w = fmaxf(fmaf(ds, acc.w, bb.w), 0.0f);
    *(uint2*)(h + (size_t)v * C + lane * 4) = f4toh4(o);
}

// ---------------------------------------------------------------------------
// Fused pool + FC head + log_softmax. batch sorted -> graph g owns contiguous
// node range; each block computes the 128-graph prefix of gcnt inline.
__global__ void k_poolhead(const __half* __restrict__ h, const float* __restrict__ Wfc,
                           const float* __restrict__ bfc, float* __restrict__ out) {
    int g = blockIdx.x;
    int t = threadIdx.x;   // 128
    __shared__ float sp[C];
    __shared__ float sl[OUTC];
    __shared__ float s_m, s_lse;
    __shared__ int sincl[NG];
    __shared__ int wtot[4];

    // inline inclusive prefix of d_gcnt (128 values, 4 warps)
    int cv = d_gcnt[t];
    int x = cv;
    #pragma unroll
    for (int o = 1; o < 32; o <<= 1) {
        int y = __shfl_up_sync(0xffffffffu, x, o);
        if ((t & 31) >= o) x += y;
    }
    if ((t & 31) == 31) wtot[t >> 5] = x;
    __syncthreads();
    int base = 0;
    #pragma unroll
    for (int wj = 0; wj < 4; wj++)
        if (wj < (t >> 5)) base += wtot[wj];
    sincl[t] = x + base;
    __syncthreads();

    int r1 = sincl[g];
    int r0 = (g > 0) ? sincl[g - 1] : 0;

    float a0 = 0.0f, a1 = 0.0f;
    int r = r0;
    for (; r + 1 < r1; r += 2) {
        a0 += __half2float(h[(size_t)r * C + t]);
        a1 += __half2float(h[(size_t)(r + 1) * C + t]);
    }
    if (r < r1) a0 += __half2float(h[(size_t)r * C + t]);
    float cnt = fmaxf((float)(r1 - r0), 1.0f);
    sp[t] = (a0 + a1) / cnt;
    __syncthreads();

    if (t < OUTC) {
        float a = bfc[t];
        #pragma unroll 8
        for (int k = 0; k < C; k++) a += sp[k] * Wfc[k * OUTC + t];
        sl[t] = a;
    }
    __syncthreads();
    if (t == 0) {
        float mx = sl[0];
        #pragma unroll
        for (int j = 1; j < OUTC; j++) mx = fmaxf(mx, sl[j]);
        float s = 0.0f;
        #pragma unroll
        for (int j = 0; j < OUTC; j++) s += expf(sl[j] - mx);
        s_m = mx;
        s_lse = logf(s);
    }
    __syncthreads();
    if (t < OUTC) out[g * OUTC + t] = sl[t] - s_m - s_lse;
}

// ---------------------------------------------------------------------------
extern "C" void kernel_launch(void* const* d_in, const int* in_sizes, int n_in,
                              void* d_out, int out_size) {
    const float* x     = (const float*)d_in[0];
    const void*  ei    = d_in[1];
    const void*  batch = d_in[2];
    const float* W1    = (const float*)d_in[3];
    const float* b1    = (const float*)d_in[4];
    const float* W2    = (const float*)d_in[5];
    const float* b2    = (const float*)d_in[6];
    const float* Wfc   = (const float*)d_in[7];
    const float* bfc   = (const float*)d_in[8];
    float* out = (float*)d_out;

    __half *hp, *h;
    cudaGetSymbolAddress((void**)&hp, d_hp);
    cudaGetSymbolAddress((void**)&h, d_h);

    k_setup<<<(NN + 255) / 256, 256>>>((const unsigned int*)ei);
    k_count_gcnt<<<(NE + 255) / 256, 256>>>(ei, batch);
    k_scan<<<NBLK, SB>>>();
    k_fill<<<(NE + 255) / 256, 256>>>(ei);

    // layer 1
    k_gemm<float><<<(NN + BM - 1) / BM, 256>>>(x, W1, hp, NN);
    k_agg<<<(NN * 32 + 255) / 256, 256>>>(hp, b1, h);

    // layer 2
    k_gemm<__half><<<(NN + BM - 1) / BM, 256>>>(h, W2, hp, NN);
    k_agg<<<(NN * 32 + 255) / 256, 256>>>(hp, b2, h);

    // fused pool + head
    k_poolhead<<<NG, C>>>(h, Wfc, bfc, out);
}

// round 14
// speedup vs baseline: 1.0997x; 1.0147x over previous
#include <cuda_runtime.h>
#include <cuda_fp16.h>
#include <math.h>
#include <stdint.h>

#define NN 50000
#define NE 800000
#define C 128
#define OUTC 16
#define NG 128
#define SB 512
#define NBLK ((NN + SB - 1) / SB)   // 98

// GEMM tiling (tf32 tensor-core)
#define BM 128
#define BK 32
#define SA_STRIDE 36    // floats; bank = (4*row + col) % 32 -> conflict-free frags
#define SW_STRIDE 136   // floats; bank = (8*k + n) % 32   -> conflict-free frags

// -------- device scratch (no allocations allowed) --------
__device__ int   d_is64;
__device__ int   d_cnt[NN];          // incoming-edge counts
__device__ int   d_off[NN + 1];      // CSR offsets
__device__ int   d_rank[NE];         // edge rank within its dst bucket
__device__ int   d_srcs[NE];         // src ids grouped by dst
__device__ int   d_state[NBLK];      // lookback state: 0=none,1=agg,2=prefix
__device__ int   d_aggv[NBLK];       // block aggregate
__device__ int   d_prefv[NBLK];      // block inclusive prefix
__device__ int   d_gcnt[NG];         // nodes per graph
__device__ float d_dis[NN];
__device__ __align__(16) __half d_hp[(size_t)NN * C];
__device__ __align__(16) __half d_h [(size_t)NN * C];

// index accessor: int64 vs int32 edge/batch arrays
__device__ __forceinline__ int eidx(const void* p, int pos) {
    return d_is64 ? (int)((const long long*)p)[pos] : ((const int*)p)[pos];
}

__device__ __forceinline__ uint32_t f2tf32(float x) {
    uint32_t r;
    asm("cvt.rna.tf32.f32 %0, %1;" : "=r"(r) : "f"(x));
    return r;
}

__device__ __forceinline__ float4 h4tof4(uint2 u) {
    __half2 a = *reinterpret_cast<__half2*>(&u.x);
    __half2 b = *reinterpret_cast<__half2*>(&u.y);
    float2 fa = __half22float2(a), fb = __half22float2(b);
    return make_float4(fa.x, fa.y, fb.x, fb.y);
}

__device__ __forceinline__ uint2 f4toh4(float4 f) {
    __half2 a = __floats2half2_rn(f.x, f.y);
    __half2 b = __floats2half2_rn(f.z, f.w);
    uint2 u;
    u.x = *reinterpret_cast<uint32_t*>(&a);
    u.y = *reinterpret_cast<uint32_t*>(&b);
    return u;
}

// ---------------------------------------------------------------------------
// setup: zero counters + lookback state; thread 0 sniffs index dtype
__global__ void k_setup(const unsigned int* __restrict__ w) {
    int i = blockIdx.x * blockDim.x + threadIdx.x;
    if (i == 0) {
        int allz = 1;
        #pragma unroll
        for (int j = 0; j < 32; j++)
            if (w[2 * j + 1] != 0u) allz = 0;
        d_is64 = allz;
    }
    if (i < NN) d_cnt[i] = 0;
    if (i < NG) d_gcnt[i] = 0;
    if (i < NBLK) d_state[i] = 0;
}

// fused: count incoming edges per dst (capturing per-edge rank) + graph counts
__global__ void k_count_gcnt(const void* __restrict__ ei, const void* __restrict__ batch) {
    int i = blockIdx.x * blockDim.x + threadIdx.x;
    if (i < NE) d_rank[i] = atomicAdd(&d_cnt[eidx(ei, NE + i)], 1);
    if (i < NN) atomicAdd(&d_gcnt[eidx(batch, i)], 1);
}

// ---------------------------------------------------------------------------
// Single-pass decoupled-lookback exclusive scan of d_cnt -> d_off;
// also computes dis = rsqrt(deg+1).
__global__ void k_scan() {
    __shared__ int wsum[16];
    __shared__ int stotal;
    __shared__ int sbase;
    int b = blockIdx.x;
    int t = threadIdx.x;
    int i = b * SB + t;
    int v = (i < NN) ? d_cnt[i] : 0;

    // intra-block inclusive scan
    int x = v;
    #pragma unroll
    for (int o = 1; o < 32; o <<= 1) {
        int y = __shfl_up_sync(0xffffffffu, x, o);
        if ((t & 31) >= o) x += y;
    }
    if ((t & 31) == 31) wsum[t >> 5] = x;
    __syncthreads();
    if (t < 16) {
        int y = wsum[t];
        #pragma unroll
        for (int o = 1; o < 16; o <<= 1) {
            int z = __shfl_up_sync(0xffffu, y, o);
            if (t >= o) y += z;
        }
        wsum[t] = y;
    }
    __syncthreads();
    int wbase = (t >= 32) ? wsum[(t >> 5) - 1] : 0;
    int incl = x + wbase;
    if (t == SB - 1) stotal = incl;
    __syncthreads();

    // publish aggregate (or prefix for block 0)
    if (t == 0) {
        if (b == 0) {
            d_prefv[0] = stotal;
            __threadfence();
            *(volatile int*)&d_state[0] = 2;
        } else {
            d_aggv[b] = stotal;
            __threadfence();
            *(volatile int*)&d_state[b] = 1;
        }
        if (b == 0) sbase = 0;
    }

    // warp 0 performs decoupled lookback
    if (b > 0 && t < 32) {
        int sum = 0;
        int j = b - 1;
        while (true) {
            int jj = j - t;
            int st = (jj >= 0) ? *(volatile int*)&d_state[jj] : 2;
            while (__any_sync(0xffffffffu, st == 0)) {
                st = (jj >= 0) ? *(volatile int*)&d_state[jj] : 2;
            }
            __threadfence();
            unsigned mask2 = __ballot_sync(0xffffffffu, st == 2 && jj >= 0);
            int val;
            bool done;
            if (mask2) {
                int lead = __ffs(mask2) - 1;       // smallest lane = largest jj with prefix
                if (t < lead)       val = *(volatile int*)&d_aggv[jj];
                else if (t == lead) val = *(volatile int*)&d_prefv[jj];
                else                val = 0;
                done = true;
            } else {
                val = (jj >= 0) ? *(volatile int*)&d_aggv[jj] : 0;
                done = false;
            }
            #pragma unroll
            for (int o = 16; o > 0; o >>= 1) val += __shfl_down_sync(0xffffffffu, val, o);
            val = __shfl_sync(0xffffffffu, val, 0);
            sum += val;
            if (done) break;
            j -= 32;
        }
        if (t == 0) {
            sbase = sum;
            d_prefv[b] = sum + stotal;
            __threadfence();
            *(volatile int*)&d_state[b] = 2;
        }
    }
    __syncthreads();

    int base = sbase;
    if (i < NN) {
        d_off[i] = incl - v + base;          // exclusive global prefix
        d_dis[i] = rsqrtf((float)(v + 1));   // +1 self loop
    }
    if (i == 0) d_off[NN] = NE;
}

// fill CSR without atomics: slot = off[dst] + rank[e]
__global__ void k_fill(const void* __restrict__ ei) {
    int e = blockIdx.x * blockDim.x + threadIdx.x;
    if (e >= NE) return;
    int s = eidx(ei, e);
    int d = eidx(ei, NE + e);
    d_srcs[d_off[d] + d_rank[e]] = s;
}

// ---------------------------------------------------------------------------
// TF32 tensor-core GEMM: hp(half) = dis[:,None] * (A @ W), A fp32 or fp16.
// 128x128 block tile, 256 threads = 8 warps (2x4), warp tile 64x32.
template <typename T>
__global__ void __launch_bounds__(256)
k_gemm(const T* __restrict__ A, const float* __restrict__ W,
       __half* __restrict__ hp, int n) {
    __shared__ uint32_t sA[BM * SA_STRIDE];   // tf32 bits, row-major, stride 36
    __shared__ uint32_t sW[BK * SW_STRIDE];   // tf32 bits, k-major, stride 136

    int tid = threadIdx.x;
    int lane = tid & 31;
    int wid = tid >> 5;
    int wm = wid >> 2;          // 0..1 : rows [wm*64, wm*64+64)
    int wn = wid & 3;           // 0..3 : cols [wn*32, wn*32+32)
    int g  = lane >> 2;         // groupID 0..7
    int tg = lane & 3;          // threadID-in-group 0..3
    int row0 = blockIdx.x * BM;

    float acc[4][4][4];         // [m-frag][n-frag][reg]
    #pragma unroll
    for (int i = 0; i < 4; i++)
        #pragma unroll
        for (int j = 0; j < 4; j++)
            #pragma unroll
            for (int r = 0; r < 4; r++) acc[i][j][r] = 0.0f;

    for (int kc = 0; kc < C / BK; kc++) {
        __syncthreads();
        // stage A chunk: 128 rows x 32 k; cvt to tf32
        #pragma unroll
        for (int p = 0; p < 4; p++) {
            int idx = tid + p * 256;        // 0..1023
            int r = idx >> 3;               // 0..127
            int c4 = idx & 7;               // 0..7
            int gr = row0 + r;
            float4 v = make_float4(0.f, 0.f, 0.f, 0.f);
            if (gr < n) {
                if constexpr (sizeof(T) == 4) {
                    v = *(const float4*)((const float*)A + (size_t)gr * C + kc * BK + c4 * 4);
                } else {
                    uint2 u = *(const uint2*)((const __half*)A + (size_t)gr * C + kc * BK + c4 * 4);
                    v = h4tof4(u);
                }
            }
            uint32_t* dst = sA + r * SA_STRIDE + c4 * 4;
            dst[0] = f2tf32(v.x); dst[1] = f2tf32(v.y);
            dst[2] = f2tf32(v.z); dst[3] = f2tf32(v.w);
        }
        // stage W chunk: 32 k x 128 n
        #pragma unroll
        for (int p = 0; p < 4; p++) {
            int idx = tid + p * 256;
            int k = idx >> 5;               // 0..31
            int n4 = idx & 31;              // 0..31
            float4 v = *(const float4*)(W + (size_t)(kc * BK + k) * C + n4 * 4);
            uint32_t* dst = sW + k * SW_STRIDE + n4 * 4;
            dst[0] = f2tf32(v.x); dst[1] = f2tf32(v.y);
            dst[2] = f2tf32(v.z); dst[3] = f2tf32(v.w);
        }
        __syncthreads();

        #pragma unroll
        for (int ks = 0; ks < BK / 8; ks++) {
            int kb = ks * 8;
            uint32_t bf[4][2];
            #pragma unroll
            for (int nt = 0; nt < 4; nt++) {
                int nn = wn * 32 + nt * 8 + g;
                bf[nt][0] = sW[(kb + tg) * SW_STRIDE + nn];
                bf[nt][1] = sW[(kb + tg + 4) * SW_STRIDE + nn];
            }
            uint32_t af[4][4];
            #pragma unroll
            for (int mt = 0; mt < 4; mt++) {
                int rbase = wm * 64 + mt * 16;
                af[mt][0] = sA[(rbase + g)     * SA_STRIDE + kb + tg];
                af[mt][1] = sA[(rbase + g + 8) * SA_STRIDE + kb + tg];
                af[mt][2] = sA[(rbase + g)     * SA_STRIDE + kb + tg + 4];
                af[mt][3] = sA[(rbase + g + 8) * SA_STRIDE + kb + tg + 4];
            }
            #pragma unroll
            for (int mt = 0; mt < 4; mt++)
                #pragma unroll
                for (int nt = 0; nt < 4; nt++) {
                    asm volatile(
                        "mma.sync.aligned.m16n8k8.row.col.f32.tf32.tf32.f32 "
                        "{%0,%1,%2,%3}, {%4,%5,%6,%7}, {%8,%9}, {%0,%1,%2,%3};"
                        : "+f"(acc[mt][nt][0]), "+f"(acc[mt][nt][1]),
                          "+f"(acc[mt][nt][2]), "+f"(acc[mt][nt][3])
                        : "r"(af[mt][0]), "r"(af[mt][1]), "r"(af[mt][2]), "r"(af[mt][3]),
                          "r"(bf[nt][0]), "r"(bf[nt][1]));
                }
        }
    }

    // epilogue: scale by dis[row], store half2 pairs
    #pragma unroll
    for (int mt = 0; mt < 4; mt++) {
        int r0 = row0 + wm * 64 + mt * 16 + g;
        int r1 = r0 + 8;
        float ds0 = (r0 < n) ? d_dis[r0] : 0.0f;
        float ds1 = (r1 < n) ? d_dis[r1] : 0.0f;
        #pragma unroll
        for (int nt = 0; nt < 4; nt++) {
            int col = wn * 32 + nt * 8 + tg * 2;
            if (r0 < n) {
                __half2 o = __floats2half2_rn(acc[mt][nt][0] * ds0, acc[mt][nt][1] * ds0);
                *(__half2*)(hp + (size_t)r0 * C + col) = o;
            }
            if (r1 < n) {
                __half2 o = __floats2half2_rn(acc[mt][nt][2] * ds1, acc[mt][nt][3] * ds1);
                *(__half2*)(hp + (size_t)r1 * C + col) = o;
            }
        }
    }
}

// ---------------------------------------------------------------------------
// Aggregate (gather, no atomics): one warp per dst node, fp16 in/out, fp32 acc.
// h[v] = relu( dis[v] * (hp[v] + sum_{e in(v)} hp[src_e]) + b )
__global__ void k_agg(const __half* __restrict__ hp, const float* __restrict__ b,
                      __half* __restrict__ h) {
    int v = (blockIdx.x * blockDim.x + threadIdx.x) >> 5;
    if (v >= NN) return;
    int lane = threadIdx.x & 31;

    float4 acc = h4tof4(*(const uint2*)(hp + (size_t)v * C + lane * 4));  // self loop
    int e = d_off[v], end = d_off[v + 1];

    for (; e + 3 < end; e += 4) {
        int s0 = d_srcs[e], s1 = d_srcs[e + 1], s2 = d_srcs[e + 2], s3 = d_srcs[e + 3];
        float4 m0 = h4tof4(*(const uint2*)(hp + (size_t)s0 * C + lane * 4));
        float4 m1 = h4tof4(*(const uint2*)(hp + (size_t)s1 * C + lane * 4));
        float4 m2 = h4tof4(*(const uint2*)(hp + (size_t)s2 * C + lane * 4));
        float4 m3 = h4tof4(*(const uint2*)(hp + (size_t)s3 * C + lane * 4));
        acc.x += m0.x + m1.x + m2.x + m3.x;
        acc.y += m0.y + m1.y + m2.y + m3.y;
        acc.z += m0.z + m1.z + m2.z + m3.z;
        acc.w += m0.w + m1.w + m2.w + m3.w;
    }
    for (; e < end; e++) {
        int s = d_srcs[e];
        float4 m = h4tof4(*(const uint2*)(hp + (size_t)s * C + lane * 4));
        acc.x += m.x; acc.y += m.y; acc.z += m.z; acc.w += m.w;
    }

    float ds = d_dis[v];
    float4 bb = ((const float4*)b)[lane];
    float4 o;
    o.x = fmaxf(fmaf(ds, acc.x, bb.x), 0.0f);
    o.y = fmaxf(fmaf(ds, acc.y, bb.y), 0.0f);
    o.z = fmaxf(fmaf(ds, acc.z, bb.z), 0.0f);
    o.w = fmaxf(fmaf(ds, acc.w, bb.w), 0.0f);
    *(uint2*)(h + (size_t)v * C + lane * 4) = f4toh4(o);
}

// ---------------------------------------------------------------------------
// Fused pool + FC head + log_softmax. batch sorted -> graph g owns contiguous
// node range; each block computes the 128-graph prefix of gcnt inline.
__global__ void k_poolhead(const __half* __restrict__ h, const float* __restrict__ Wfc,
                           const float* __restrict__ bfc, float* __restrict__ out) {
    int g = blockIdx.x;
    int t = threadIdx.x;   // 128
    __shared__ float sp[C];
    __shared__ float sl[OUTC];
    __shared__ float s_m, s_lse;
    __shared__ int sincl[NG];
    __shared__ int wtot[4];

    // inline inclusive prefix of d_gcnt (128 values, 4 warps)
    int cv = d_gcnt[t];
    int x = cv;
    #pragma unroll
    for (int o = 1; o < 32; o <<= 1) {
        int y = __shfl_up_sync(0xffffffffu, x, o);
        if ((t & 31) >= o) x += y;
    }
    if ((t & 31) == 31) wtot[t >> 5] = x;
    __syncthreads();
    int base = 0;
    #pragma unroll
    for (int wj = 0; wj < 4; wj++)
        if (wj < (t >> 5)) base += wtot[wj];
    sincl[t] = x + base;
    __syncthreads();

    int r1 = sincl[g];
    int r0 = (g > 0) ? sincl[g - 1] : 0;

    float a0 = 0.0f, a1 = 0.0f;
    int r = r0;
    for (; r + 1 < r1; r += 2) {
        a0 += __half2float(h[(size_t)r * C + t]);
        a1 += __half2float(h[(size_t)(r + 1) * C + t]);
    }
    if (r < r1) a0 += __half2float(h[(size_t)r * C + t]);
    float cnt = fmaxf((float)(r1 - r0), 1.0f);
    sp[t] = (a0 + a1) / cnt;
    __syncthreads();

    if (t < OUTC) {
        float a = bfc[t];
        #pragma unroll 8
        for (int k = 0; k < C; k++) a += sp[k] * Wfc[k * OUTC + t];
        sl[t] = a;
    }
    __syncthreads();
    if (t == 0) {
        float mx = sl[0];
        #pragma unroll
        for (int j = 1; j < OUTC; j++) mx = fmaxf(mx, sl[j]);
        float s = 0.0f;
        #pragma unroll
        for (int j = 0; j < OUTC; j++) s += expf(sl[j] - mx);
        s_m = mx;
        s_lse = logf(s);
    }
    __syncthreads();
    if (t < OUTC) out[g * OUTC + t] = sl[t] - s_m - s_lse;
}

// ---------------------------------------------------------------------------
extern "C" void kernel_launch(void* const* d_in, const int* in_sizes, int n_in,
                              void* d_out, int out_size) {
    const float* x     = (const float*)d_in[0];
    const void*  ei    = d_in[1];
    const void*  batch = d_in[2];
    const float* W1    = (const float*)d_in[3];
    const float* b1    = (const float*)d_in[4];
    const float* W2    = (const float*)d_in[5];
    const float* b2    = (const float*)d_in[6];
    const float* Wfc   = (const float*)d_in[7];
    const float* bfc   = (const float*)d_in[8];
    float* out = (float*)d_out;

    __half *hp, *h;
    cudaGetSymbolAddress((void**)&hp, d_hp);
    cudaGetSymbolAddress((void**)&h, d_h);

    k_setup<<<(NN + 255) / 256, 256>>>((const unsigned int*)ei);
    k_count_gcnt<<<(NE + 255) / 256, 256>>>(ei, batch);
    k_scan<<<NBLK, SB>>>();
    k_fill<<<(NE + 255) / 256, 256>>>(ei);

    // layer 1
    k_gemm<float><<<(NN + BM - 1) / BM, 256>>>(x, W1, hp, NN);
    k_agg<<<(NN * 32 + 255) / 256, 256>>>(hp, b1, h);

    // layer 2
    k_gemm<__half><<<(NN + BM - 1) / BM, 256>>>(h, W2, hp, NN);
    k_agg<<<(NN * 32 + 255) / 256, 256>>>(hp, b2, h);

    // fused pool + head
    k_poolhead<<<NG, C>>>(h, Wfc, bfc, out);
}

// round 15
// speedup vs baseline: 1.1130x; 1.0120x over previous
#include <cuda_runtime.h>
#include <cuda_fp16.h>
#include <math.h>
#include <stdint.h>

#define NN 50000
#define NE 800000
#define C 128
#define OUTC 16
#define NG 128
#define SB 512
#define NBLK ((NN + SB - 1) / SB)   // 98

// GEMM tiling (tf32 tensor-core)
#define BM 128
#define BK 32
#define SA_STRIDE 36    // floats; bank = (4*row + col) % 32 -> conflict-free frags
#define SW_STRIDE 136   // floats; bank = (8*k + n) % 32   -> conflict-free frags

// -------- device scratch (no allocations allowed; statics start zeroed and
// every call re-zeroes what it dirtied, so replays are deterministic) --------
__device__ int   d_cnt[NN];          // incoming-edge counts   (zeroed by k_fill)
__device__ int   d_off[NN + 1];      // CSR offsets            (overwritten each call)
__device__ int   d_rank[NE];         // edge rank within dst   (overwritten each call)
__device__ int   d_srcs[NE];         // src ids grouped by dst (overwritten each call)
__device__ int   d_state[NBLK];      // lookback state         (zeroed by k_fill)
__device__ int   d_aggv[NBLK];       // block aggregate        (state-guarded)
__device__ int   d_prefv[NBLK];      // block inclusive prefix (state-guarded)
__device__ int   d_gcnt[NG];         // nodes per graph        (zeroed by k_scan blk0)
__device__ int   d_gstart[NG + 1];   // graph start offsets    (overwritten each call)
__device__ float d_dis[NN];
__device__ __align__(16) __half d_hp[(size_t)NN * C];
__device__ __align__(16) __half d_h [(size_t)NN * C];

// block-local dtype sniff: int64 arrays have all-zero odd 32-bit words
__device__ __forceinline__ int sniff64(const unsigned int* w) {
    int allz = 1;
    #pragma unroll
    for (int j = 0; j < 32; j++)
        if (w[2 * j + 1] != 0u) allz = 0;
    return allz;
}

__device__ __forceinline__ int eidx2(const void* p, int pos, int is64) {
    return is64 ? (int)((const long long*)p)[pos] : ((const int*)p)[pos];
}

__device__ __forceinline__ uint32_t f2tf32(float x) {
    uint32_t r;
    asm("cvt.rna.tf32.f32 %0, %1;" : "=r"(r) : "f"(x));
    return r;
}

__device__ __forceinline__ float4 h4tof4(uint2 u) {
    __half2 a = *reinterpret_cast<__half2*>(&u.x);
    __half2 b = *reinterpret_cast<__half2*>(&u.y);
    float2 fa = __half22float2(a), fb = __half22float2(b);
    return make_float4(fa.x, fa.y, fb.x, fb.y);
}

__device__ __forceinline__ uint2 f4toh4(float4 f) {
    __half2 a = __floats2half2_rn(f.x, f.y);
    __half2 b = __floats2half2_rn(f.z, f.w);
    uint2 u;
    u.x = *reinterpret_cast<uint32_t*>(&a);
    u.y = *reinterpret_cast<uint32_t*>(&b);
    return u;
}

// ---------------------------------------------------------------------------
// count incoming edges per dst (capturing per-edge rank) + graph node counts
__global__ void k_count_gcnt(const void* __restrict__ ei, const void* __restrict__ batch) {
    __shared__ int s64;
    if (threadIdx.x == 0) s64 = sniff64((const unsigned int*)ei);
    __syncthreads();
    int is64 = s64;
    int i = blockIdx.x * blockDim.x + threadIdx.x;
    if (i < NE) d_rank[i] = atomicAdd(&d_cnt[eidx2(ei, NE + i, is64)], 1);
    if (i < NN) atomicAdd(&d_gcnt[eidx2(batch, i, is64)], 1);
}

// ---------------------------------------------------------------------------
// Single-pass decoupled-lookback exclusive scan of d_cnt -> d_off;
// computes dis = rsqrt(deg+1); block 0 also builds d_gstart and zeroes d_gcnt.
__global__ void k_scan() {
    __shared__ int wsum[16];
    __shared__ int stotal;
    __shared__ int sbase;
    int b = blockIdx.x;
    int t = threadIdx.x;
    int i = b * SB + t;
    int v = (i < NN) ? d_cnt[i] : 0;

    // intra-block inclusive scan
    int x = v;
    #pragma unroll
    for (int o = 1; o < 32; o <<= 1) {
        int y = __shfl_up_sync(0xffffffffu, x, o);
        if ((t & 31) >= o) x += y;
    }
    if ((t & 31) == 31) wsum[t >> 5] = x;
    __syncthreads();
    if (t < 16) {
        int y = wsum[t];
        #pragma unroll
        for (int o = 1; o < 16; o <<= 1) {
            int z = __shfl_up_sync(0xffffu, y, o);
            if (t >= o) y += z;
        }
        wsum[t] = y;
    }
    __syncthreads();
    int wbase = (t >= 32) ? wsum[(t >> 5) - 1] : 0;
    int incl = x + wbase;
    if (t == SB - 1) stotal = incl;
    __syncthreads();

    // publish aggregate (or prefix for block 0)
    if (t == 0) {
        if (b == 0) {
            d_prefv[0] = stotal;
            __threadfence();
            *(volatile int*)&d_state[0] = 2;
        } else {
            d_aggv[b] = stotal;
            __threadfence();
            *(volatile int*)&d_state[b] = 1;
        }
        if (b == 0) sbase = 0;
    }

    // warp 0 performs decoupled lookback
    if (b > 0 && t < 32) {
        int sum = 0;
        int j = b - 1;
        while (true) {
            int jj = j - t;
            int st = (jj >= 0) ? *(volatile int*)&d_state[jj] : 2;
            while (__any_sync(0xffffffffu, st == 0)) {
                st = (jj >= 0) ? *(volatile int*)&d_state[jj] : 2;
            }
            __threadfence();
            unsigned mask2 = __ballot_sync(0xffffffffu, st == 2 && jj >= 0);
            int val;
            bool done;
            if (mask2) {
                int lead = __ffs(mask2) - 1;
                if (t < lead)       val = *(volatile int*)&d_aggv[jj];
                else if (t == lead) val = *(volatile int*)&d_prefv[jj];
                else                val = 0;
                done = true;
            } else {
                val = (jj >= 0) ? *(volatile int*)&d_aggv[jj] : 0;
                done = false;
            }
            #pragma unroll
            for (int o = 16; o > 0; o >>= 1) val += __shfl_down_sync(0xffffffffu, val, o);
            val = __shfl_sync(0xffffffffu, val, 0);
            sum += val;
            if (done) break;
            j -= 32;
        }
        if (t == 0) {
            sbase = sum;
            d_prefv[b] = sum + stotal;
            __threadfence();
            *(volatile int*)&d_state[b] = 2;
        }
    }
    __syncthreads();

    int base = sbase;
    if (i < NN) {
        d_off[i] = incl - v + base;          // exclusive global prefix
        d_dis[i] = rsqrtf((float)(v + 1));   // +1 self loop
    }
    if (i == 0) d_off[NN] = NE;

    // block 0: gstart = exclusive prefix of gcnt (4 graphs per lane); zero gcnt
    if (b == 0 && t < 32) {
        int g0 = d_gcnt[4 * t],     g1 = d_gcnt[4 * t + 1];
        int g2 = d_gcnt[4 * t + 2], g3 = d_gcnt[4 * t + 3];
        int tot = g0 + g1 + g2 + g3;
        int xs = tot;
        #pragma unroll
        for (int o = 1; o < 32; o <<= 1) {
            int y = __shfl_up_sync(0xffffffffu, xs, o);
            if (t >= o) xs += y;
        }
        int excl = xs - tot;
        d_gstart[4 * t + 1] = excl + g0;
        d_gstart[4 * t + 2] = excl + g0 + g1;
        d_gstart[4 * t + 3] = excl + g0 + g1 + g2;
        d_gstart[4 * t + 4] = excl + tot;
        if (t == 0) d_gstart[0] = 0;
        d_gcnt[4 * t] = 0; d_gcnt[4 * t + 1] = 0;
        d_gcnt[4 * t + 2] = 0; d_gcnt[4 * t + 3] = 0;
    }
}

// fill CSR without atomics: slot = off[dst] + rank[e]; also cleanup-zero
// d_cnt and d_state for the next call (scan already consumed them).
__global__ void k_fill(const void* __restrict__ ei) {
    __shared__ int s64;
    if (threadIdx.x == 0) s64 = sniff64((const unsigned int*)ei);
    __syncthreads();
    int is64 = s64;
    int e = blockIdx.x * blockDim.x + threadIdx.x;
    if (e < NN) d_cnt[e] = 0;
    if (e < NBLK) d_state[e] = 0;
    if (e >= NE) return;
    int s = eidx2(ei, e, is64);
    int d = eidx2(ei, NE + e, is64);
    d_srcs[d_off[d] + d_rank[e]] = s;
}

// ---------------------------------------------------------------------------
// TF32 tensor-core GEMM: hp(half) = dis[:,None] * (A @ W), A fp32 or fp16.
// 128x128 block tile, 256 threads = 8 warps (2x4), warp tile 64x32.
// Register double-buffer: chunk kc+1 is fetched to registers during kc's MMAs.
template <typename T>
__global__ void __launch_bounds__(256)
k_gemm(const T* __restrict__ A, const float* __restrict__ W,
       __half* __restrict__ hp, int n) {
    __shared__ uint32_t sA[BM * SA_STRIDE];   // tf32 bits, row-major, stride 36
    __shared__ uint32_t sW[BK * SW_STRIDE];   // tf32 bits, k-major, stride 136

    int tid = threadIdx.x;
    int lane = tid & 31;
    int wid = tid >> 5;
    int wm = wid >> 2;          // 0..1 : rows [wm*64, wm*64+64)
    int wn = wid & 3;           // 0..3 : cols [wn*32, wn*32+32)
    int g  = lane >> 2;         // groupID 0..7
    int tg = lane & 3;          // threadID-in-group 0..3
    int row0 = blockIdx.x * BM;

    // A-staging geometry: idx = tid + p*256 -> row = idx>>3, c4 = idx&7
    int ar = tid >> 3;          // base row for p stepping (+32 per p)
    int ac4 = tid & 7;
    // W-staging geometry: k = idx>>5, n4 = idx&31
    int wk = tid >> 5;          // +8 per p
    int wn4 = tid & 31;

    float4 rA[4], rW[4];

    // prefetch chunk 0
    #pragma unroll
    for (int p = 0; p < 4; p++) {
        int gr = row0 + ar + p * 32;
        float4 v = make_float4(0.f, 0.f, 0.f, 0.f);
        if (gr < n) {
            if constexpr (sizeof(T) == 4)
                v = *(const float4*)((const float*)A + (size_t)gr * C + ac4 * 4);
            else
                v = h4tof4(*(const uint2*)((const __half*)A + (size_t)gr * C + ac4 * 4));
        }
        rA[p] = v;
        rW[p] = *(const float4*)(W + (size_t)(wk + p * 8) * C + wn4 * 4);
    }

    float acc[4][4][4];
    #pragma unroll
    for (int i = 0; i < 4; i++)
        #pragma unroll
        for (int j = 0; j < 4; j++)
            #pragma unroll
            for (int r = 0; r < 4; r++) acc[i][j][r] = 0.0f;

    for (int kc = 0; kc < C / BK; kc++) {
        // store staged registers to smem (cvt to tf32)
        #pragma unroll
        for (int p = 0; p < 4; p++) {
            uint32_t* dstA = sA + (ar + p * 32) * SA_STRIDE + ac4 * 4;
            dstA[0] = f2tf32(rA[p].x); dstA[1] = f2tf32(rA[p].y);
            dstA[2] = f2tf32(rA[p].z); dstA[3] = f2tf32(rA[p].w);
            uint32_t* dstW = sW + (wk + p * 8) * SW_STRIDE + wn4 * 4;
            dstW[0] = f2tf32(rW[p].x); dstW[1] = f2tf32(rW[p].y);
            dstW[2] = f2tf32(rW[p].z); dstW[3] = f2tf32(rW[p].w);
        }
        __syncthreads();

        // prefetch next chunk while MMAs run
        if (kc + 1 < C / BK) {
            int koff = (kc + 1) * BK;
            #pragma unroll
            for (int p = 0; p < 4; p++) {
                int gr = row0 + ar + p * 32;
                float4 v = make_float4(0.f, 0.f, 0.f, 0.f);
                if (gr < n) {
                    if constexpr (sizeof(T) == 4)
                        v = *(const float4*)((const float*)A + (size_t)gr * C + koff + ac4 * 4);
                    else
                        v = h4tof4(*(const uint2*)((const __half*)A + (size_t)gr * C + koff + ac4 * 4));
                }
                rA[p] = v;
                rW[p] = *(const float4*)(W + (size_t)(koff + wk + p * 8) * C + wn4 * 4);
            }
        }

        #pragma unroll
        for (int ks = 0; ks < BK / 8; ks++) {
            int kb = ks * 8;
            uint32_t bf[4][2];
            #pragma unroll
            for (int nt = 0; nt < 4; nt++) {
                int nn = wn * 32 + nt * 8 + g;
                bf[nt][0] = sW[(kb + tg) * SW_STRIDE + nn];
                bf[nt][1] = sW[(kb + tg + 4) * SW_STRIDE + nn];
            }
            uint32_t af[4][4];
            #pragma unroll
            for (int mt = 0; mt < 4; mt++) {
                int rbase = wm * 64 + mt * 16;
                af[mt][0] = sA[(rbase + g)     * SA_STRIDE + kb + tg];
                af[mt][1] = sA[(rbase + g + 8) * SA_STRIDE + kb + tg];
                af[mt][2] = sA[(rbase + g)     * SA_STRIDE + kb + tg + 4];
                af[mt][3] = sA[(rbase + g + 8) * SA_STRIDE + kb + tg + 4];
            }
            #pragma unroll
            for (int mt = 0; mt < 4; mt++)
                #pragma unroll
                for (int nt = 0; nt < 4; nt++) {
                    asm volatile(
                        "mma.sync.aligned.m16n8k8.row.col.f32.tf32.tf32.f32 "
                        "{%0,%1,%2,%3}, {%4,%5,%6,%7}, {%8,%9}, {%0,%1,%2,%3};"
                        : "+f"(acc[mt][nt][0]), "+f"(acc[mt][nt][1]),
                          "+f"(acc[mt][nt][2]), "+f"(acc[mt][nt][3])
                        : "r"(af[mt][0]), "r"(af[mt][1]), "r"(af[mt][2]), "r"(af[mt][3]),
                          "r"(bf[nt][0]), "r"(bf[nt][1]));
                }
        }
        __syncthreads();
    }

    // epilogue: scale by dis[row], store half2 pairs
    #pragma unroll
    for (int mt = 0; mt < 4; mt++) {
        int r0 = row0 + wm * 64 + mt * 16 + g;
        int r1 = r0 + 8;
        float ds0 = (r0 < n) ? d_dis[r0] : 0.0f;
        float ds1 = (r1 < n) ? d_dis[r1] : 0.0f;
        #pragma unroll
        for (int nt = 0; nt < 4; nt++) {
            int col = wn * 32 + nt * 8 + tg * 2;
            if (r0 < n) {
                __half2 o = __floats2half2_rn(acc[mt][nt][0] * ds0, acc[mt][nt][1] * ds0);
                *(__half2*)(hp + (size_t)r0 * C + col) = o;
            }
            if (r1 < n) {
                __half2 o = __floats2half2_rn(acc[mt][nt][2] * ds1, acc[mt][nt][3] * ds1);
                *(__half2*)(hp + (size_t)r1 * C + col) = o;
            }
        }
    }
}

// ---------------------------------------------------------------------------
// Aggregate (gather, no atomics): one warp per dst node, fp16 in/out, fp32 acc.
// h[v] = relu( dis[v] * (hp[v] + sum_{e in(v)} hp[src_e]) + b )
__global__ void k_agg(const __half* __restrict__ hp, const float* __restrict__ b,
                      __half* __restrict__ h) {
    int v = (blockIdx.x * blockDim.x + threadIdx.x) >> 5;
    if (v >= NN) return;
    int lane = threadIdx.x & 31;

    float4 acc = h4tof4(*(const uint2*)(hp + (size_t)v * C + lane * 4));  // self loop
    int e = d_off[v], end = d_off[v + 1];

    for (; e + 3 < end; e += 4) {
        int s0 = d_srcs[e], s1 = d_srcs[e + 1], s2 = d_srcs[e + 2], s3 = d_srcs[e + 3];
        float4 m0 = h4tof4(*(const uint2*)(hp + (size_t)s0 * C + lane * 4));
        float4 m1 = h4tof4(*(const uint2*)(hp + (size_t)s1 * C + lane * 4));
        float4 m2 = h4tof4(*(const uint2*)(hp + (size_t)s2 * C + lane * 4));
        float4 m3 = h4tof4(*(const uint2*)(hp + (size_t)s3 * C + lane * 4));
        acc.x += m0.x + m1.x + m2.x + m3.x;
        acc.y += m0.y + m1.y + m2.y + m3.y;
        acc.z += m0.z + m1.z + m2.z + m3.z;
        acc.w += m0.w + m1.w + m2.w + m3.w;
    }
    for (; e < end; e++) {
        int s = d_srcs[e];
        float4 m = h4tof4(*(const uint2*)(hp + (size_t)s * C + lane * 4));
        acc.x += m.x; acc.y += m.y; acc.z += m.z; acc.w += m.w;
    }

    float ds = d_dis[v];
    float4 bb = ((const float4*)b)[lane];
    float4 o;
    o.x = fmaxf(fmaf(ds, acc.x, bb.x), 0.0f);
    o.y = fmaxf(fmaf(ds, acc.y, bb.y), 0.0f);
    o.z = fmaxf(fmaf(ds, acc.z, bb.z), 0.0f);
    o.w = fmaxf(fmaf(ds, acc.w, bb.w), 0.0f);
    *(uint2*)(h + (size_t)v * C + lane * 4) = f4toh4(o);
}

// ---------------------------------------------------------------------------
// Fused pool + FC head + log_softmax using precomputed d_gstart.
__global__ void k_poolhead(const __half* __restrict__ h, const float* __restrict__ Wfc,
                           const float* __restrict__ bfc, float* __restrict__ out) {
    int g = blockIdx.x;
    int t = threadIdx.x;   // 128
    __shared__ float sp[C];
    __shared__ float sl[OUTC];
    __shared__ float s_m, s_lse;

    int r0 = d_gstart[g], r1 = d_gstart[g + 1];

    float a0 = 0.0f, a1 = 0.0f;
    int r = r0;
    for (; r + 1 < r1; r += 2) {
        a0 += __half2float(h[(size_t)r * C + t]);
        a1 += __half2float(h[(size_t)(r + 1) * C + t]);
    }
    if (r < r1) a0 += __half2float(h[(size_t)r * C + t]);
    float cnt = fmaxf((float)(r1 - r0), 1.0f);
    sp[t] = (a0 + a1) / cnt;
    __syncthreads();

    if (t < OUTC) {
        float a = bfc[t];
        #pragma unroll 8
        for (int k = 0; k < C; k++) a += sp[k] * Wfc[k * OUTC + t];
        sl[t] = a;
    }
    __syncthreads();
    if (t == 0) {
        float mx = sl[0];
        #pragma unroll
        for (int j = 1; j < OUTC; j++) mx = fmaxf(mx, sl[j]);
        float s = 0.0f;
        #pragma unroll
        for (int j = 0; j < OUTC; j++) s += expf(sl[j] - mx);
        s_m = mx;
        s_lse = logf(s);
    }
    __syncthreads();
    if (t < OUTC) out[g * OUTC + t] = sl[t] - s_m - s_lse;
}

// ---------------------------------------------------------------------------
extern "C" void kernel_launch(void* const* d_in, const int* in_sizes, int n_in,
                              void* d_out, int out_size) {
    const float* x     = (const float*)d_in[0];
    const void*  ei    = d_in[1];
    const void*  batch = d_in[2];
    const float* W1    = (const float*)d_in[3];
    const float* b1    = (const float*)d_in[4];
    const float* W2    = (const float*)d_in[5];
    const float* b2    = (const float*)d_in[6];
    const float* Wfc   = (const float*)d_in[7];
    const float* bfc   = (const float*)d_in[8];
    float* out = (float*)d_out;

    __half *hp, *h;
    cudaGetSymbolAddress((void**)&hp, d_hp);
    cudaGetSymbolAddress((void**)&h, d_h);

    k_count_gcnt<<<(NE + 255) / 256, 256>>>(ei, batch);
    k_scan<<<NBLK, SB>>>();
    k_fill<<<(NE + 255) / 256, 256>>>(ei);

    // layer 1
    k_gemm<float><<<(NN + BM - 1) / BM, 256>>>(x, W1, hp, NN);
    k_agg<<<(NN * 32 + 255) / 256, 256>>>(hp, b1, h);

    // layer 2
    k_gemm<__half><<<(NN + BM - 1) / BM, 256>>>(h, W2, hp, NN);
    k_agg<<<(NN * 32 + 255) / 256, 256>>>(hp, b2, h);

    // fused pool + head
    k_poolhead<<<NG, C>>>(h, Wfc, bfc, out);
}